// round 3
// baseline (speedup 1.0000x reference)
#include <cuda_runtime.h>
#include <cstdint>
#include <cfloat>

// Problem constants (fixed shapes from setup_inputs):
//   x: (B=32, C=64, H=64, W=64) fp32   -> N = B*H*W = 131072 vectors of dim 64
//   codebook: (K=1024, D=64) fp32
// Output: z_q (32*64*64*64 fp32) followed by scalar vq_loss.
//
// CRITICAL: the reference's d2 = (x_sq + e_sq) - (2*flat)@cb.T is quantized to
// ulp(~64) = 7.6e-6 while inter-code gaps are often smaller -> the argmin is
// decided by the reference's own fp32 rounding. We bit-emulate it:
//   x_sq : sequential scalar fp32  s = fadd(s, fmul(x,x))    (XLA CPU reduce)
//   m    : sequential fused-FMA chain over d ascending        (Eigen gemm)
//   d2   : fsub(fadd(x_sq, e_sq), m)                          (two roundings)
//   ties : lowest index                                       (jnp.argmin)

#define N_VEC     131072
#define DIM       64
#define K_CODES   1024
#define HWSZ      4096
#define POS_PER_BLK 128
#define NBLK      (N_VEC / POS_PER_BLK)      // 1024
#define CODES_PER_TILE 64
#define N_TILES   (K_CODES / CODES_PER_TILE) // 16
#define THREADS   256

__device__ float g_esq[K_CODES];
__device__ float g_partial[NBLK];

// ---- packed fp32x2 helpers (Blackwell FFMA2 path; each half is a
//      correctly-rounded fused FMA, bit-identical to scalar fmaf) ----
__device__ __forceinline__ unsigned long long pack2(float lo, float hi) {
    unsigned long long r;
    asm("mov.b64 %0, {%1, %2};" : "=l"(r) : "r"(__float_as_uint(lo)), "r"(__float_as_uint(hi)));
    return r;
}
__device__ __forceinline__ void unpack2(unsigned long long v, float &lo, float &hi) {
    unsigned int a, b;
    asm("mov.b64 {%0, %1}, %2;" : "=r"(a), "=r"(b) : "l"(v));
    lo = __uint_as_float(a);
    hi = __uint_as_float(b);
}
__device__ __forceinline__ void fma2(unsigned long long &d, unsigned long long a, unsigned long long b) {
    asm("fma.rn.f32x2 %0, %1, %2, %0;" : "+l"(d) : "l"(a), "l"(b));
}

// ---- codebook squared-norms: sequential fp32, separate mul/add roundings ----
__global__ void esq_kernel(const float* __restrict__ cb) {
    int k = blockIdx.x * blockDim.x + threadIdx.x;
    if (k < K_CODES) {
        const float* row = cb + (size_t)k * DIM;
        float s = 0.f;
#pragma unroll
        for (int d = 0; d < DIM; ++d) {
            float v = row[d];
            s = __fadd_rn(s, __fmul_rn(v, v));
        }
        g_esq[k] = s;
    }
}

// ---- main kernel: fused distances + argmin + gather + per-block SSE ----
__global__ void __launch_bounds__(THREADS)
vq_main(const float* __restrict__ x, const float* __restrict__ cb, float* __restrict__ out) {
    extern __shared__ float sm[];
    float* x_sT  = sm;                        // [64][128] holds 2*x, d-major
    float* e_s   = x_sT + DIM * POS_PER_BLK;  // [64 codes][65] padded
    float* esq   = e_s + CODES_PER_TILE * 65; // [1024]
    float* red   = esq + K_CODES;             // [256]
    float* xsq_s = red + THREADS;             // [128]
    int*   bidx  = (int*)(xsq_s + POS_PER_BLK); // [128]

    const int tid = threadIdx.x;
    const int n0  = blockIdx.x * POS_PER_BLK;
    const int b   = n0 >> 12;
    const int hw0 = n0 & (HWSZ - 1);
    const float* xb = x + (size_t)b * DIM * HWSZ + hw0;

    // Load x tile scaled by 2 (exact). GMEM already [d][spatial] -> direct copy.
#pragma unroll
    for (int it = 0; it < (DIM * POS_PER_BLK) / THREADS; ++it) {
        int e = it * THREADS + tid;
        int d = e >> 7, i = e & 127;
        x_sT[d * POS_PER_BLK + i] = 2.0f * xb[(size_t)d * HWSZ + i];
    }
#pragma unroll
    for (int it = 0; it < K_CODES / THREADS; ++it)
        esq[it * THREADS + tid] = g_esq[it * THREADS + tid];
    __syncthreads();

    // x_sq per position, emulating XLA CPU sequential reduce of flat*flat:
    // term = fl(x*x) recovered exactly from the 2x tile: fl((2x)^2) * 0.25.
    if (tid < POS_PER_BLK) {
        float s = 0.f;
#pragma unroll
        for (int d = 0; d < DIM; ++d) {
            float xv = x_sT[d * POS_PER_BLK + tid];           // 2x
            float t  = __fmul_rn(__fmul_rn(xv, xv), 0.25f);   // = fl(x*x) exactly
            s = __fadd_rn(s, t);
        }
        xsq_s[tid] = s;
    }

    const int pg = tid >> 4;   // 0..15  position group (8 positions each)
    const int cg = tid & 15;   // 0..15  code group (4 codes per tile each)
    const int pbase = pg * 8;
    const int cbase = cg * 4;

    float bestS[8];
    int   bestI[8];
#pragma unroll
    for (int p = 0; p < 8; ++p) { bestS[p] = FLT_MAX; bestI[p] = 0; }

    for (int t = 0; t < N_TILES; ++t) {
        __syncthreads();
#pragma unroll
        for (int it = 0; it < (CODES_PER_TILE * DIM) / THREADS; ++it) {
            int e = it * THREADS + tid;
            int c = e >> 6, d = e & 63;
            e_s[c * 65 + d] = cb[(size_t)(t * CODES_PER_TILE + c) * DIM + d];
        }
        __syncthreads();

        // m_k = sequential fused-FMA chain over d ascending of (2x_d)*e_kd,
        // matching Eigen's gebp accumulation (one accumulator, k ascending).
        unsigned long long acc[4][4];
#pragma unroll
        for (int u = 0; u < 4; ++u)
#pragma unroll
            for (int j = 0; j < 4; ++j) acc[u][j] = 0ull;

#pragma unroll 8
        for (int d = 0; d < DIM; ++d) {
            unsigned long long xv[4], ep[4];
#pragma unroll
            for (int u = 0; u < 4; ++u)
                xv[u] = *reinterpret_cast<const unsigned long long*>(
                    x_sT + d * POS_PER_BLK + pbase + 2 * u);
#pragma unroll
            for (int j = 0; j < 4; ++j) {
                float ev = e_s[(cbase + j) * 65 + d];
                ep[j] = pack2(ev, ev);
            }
#pragma unroll
            for (int u = 0; u < 4; ++u)
#pragma unroll
                for (int j = 0; j < 4; ++j)
                    fma2(acc[u][j], xv[u], ep[j]);
        }

        // d2 = fl( fl(x_sq + e_sq_k) - m_k ), exactly two roundings as in ref.
#pragma unroll
        for (int j = 0; j < 4; ++j) {
            int c = t * CODES_PER_TILE + cbase + j;
            float eq = esq[c];
#pragma unroll
            for (int u = 0; u < 4; ++u) {
                float lo, hi;
                unpack2(acc[u][j], lo, hi);
                float t0 = __fadd_rn(xsq_s[pbase + 2 * u],     eq);
                float t1 = __fadd_rn(xsq_s[pbase + 2 * u + 1], eq);
                float s0 = __fsub_rn(t0, lo);
                float s1 = __fsub_rn(t1, hi);
                if (s0 < bestS[2 * u])     { bestS[2 * u] = s0;     bestI[2 * u] = c; }
                if (s1 < bestS[2 * u + 1]) { bestS[2 * u + 1] = s1; bestI[2 * u + 1] = c; }
            }
        }
    }

    // Cross-thread argmin over the 16 code-group lanes; ties -> smaller index
    // (matches jnp.argmin first-occurrence semantics).
#pragma unroll
    for (int p = 0; p < 8; ++p) {
        float s = bestS[p];
        int   i = bestI[p];
#pragma unroll
        for (int o = 8; o >= 1; o >>= 1) {
            float s2 = __shfl_xor_sync(0xFFFFFFFFu, s, o);
            int   i2 = __shfl_xor_sync(0xFFFFFFFFu, i, o);
            if (s2 < s || (s2 == s && i2 < i)) { s = s2; i = i2; }
        }
        if (cg == 0) bidx[pbase + p] = i;
    }
    __syncthreads();

    // Epilogue: gather chosen codes, write z_q (coalesced), accumulate SSE.
    float sse = 0.f;
    float* ob = out + (size_t)b * DIM * HWSZ + hw0;
#pragma unroll
    for (int it = 0; it < (DIM * POS_PER_BLK) / THREADS; ++it) {
        int e = it * THREADS + tid;
        int d = e >> 7, i = e & 127;
        float q  = cb[(size_t)bidx[i] * DIM + d];
        float xv = 0.5f * x_sT[d * POS_PER_BLK + i];  // recover x exactly
        float df = xv - q;
        sse += df * df;
        ob[(size_t)d * HWSZ + i] = q;
    }
    red[tid] = sse;
    __syncthreads();
#pragma unroll
    for (int o = THREADS / 2; o > 0; o >>= 1) {
        if (tid < o) red[tid] += red[tid + o];
        __syncthreads();
    }
    if (tid == 0) g_partial[blockIdx.x] = red[0];
}

// ---- deterministic loss finalize ----
__global__ void finalize_kernel(float* __restrict__ out, int out_size) {
    __shared__ float red[256];
    int tid = threadIdx.x;
    float s = 0.f;
    for (int i = tid; i < NBLK; i += 256) s += g_partial[i];
    red[tid] = s;
    __syncthreads();
#pragma unroll
    for (int o = 128; o > 0; o >>= 1) {
        if (tid < o) red[tid] += red[tid + o];
        __syncthreads();
    }
    if (tid == 0) {
        float mse = red[0] / (float)(N_VEC * DIM);
        out[out_size - 1] = mse + 0.25f * mse;   // vq_loss = 1.25 * mse
    }
}

extern "C" void kernel_launch(void* const* d_in, const int* in_sizes, int n_in,
                              void* d_out, int out_size) {
    const float* x  = (const float*)d_in[0];
    const float* cb = (const float*)d_in[1];
    float* out = (float*)d_out;

    const int smem_bytes = (DIM * POS_PER_BLK + CODES_PER_TILE * 65 + K_CODES
                            + THREADS + POS_PER_BLK) * 4 + POS_PER_BLK * 4;
    cudaFuncSetAttribute(vq_main, cudaFuncAttributeMaxDynamicSharedMemorySize, smem_bytes);

    esq_kernel<<<K_CODES / THREADS, THREADS>>>(cb);
    vq_main<<<NBLK, THREADS, smem_bytes>>>(x, cb, out);
    finalize_kernel<<<1, 256>>>(out, out_size);
}